// round 15
// baseline (speedup 1.0000x reference)
#include <cuda_runtime.h>
#include <cstdint>

#define UNITS   2048
#define IN_DIM  512
#define TSTEPS  8192
#define NCTA    128
#define SCAN_THREADS 256
#define NCTR    16          // counters, one 128B line each
#define CTR_STRIDE 32       // 32 uints = 128B

// 64 MB staging buffer for xin = x @ wax^T + ba
__device__ float g_xin[(size_t)TSTEPS * UNITS];
// 16 counting barriers on distinct L2 lines: CTA i bumps counter i&15.
// Step t complete <=> every counter >= 8*t.
__device__ unsigned g_ctrs[NCTR * CTR_STRIDE];

__device__ __forceinline__ unsigned ld_relaxed_gpu(const unsigned* p) {
    unsigned v;
    asm volatile("ld.relaxed.gpu.u32 %0, [%1];" : "=r"(v) : "l"(p) : "memory");
    return v;
}
__device__ __forceinline__ void red_release_add(unsigned* p, unsigned v) {
    asm volatile("red.release.gpu.global.add.u32 [%0], %1;"
                 :: "l"(p), "r"(v) : "memory");
}
__device__ __forceinline__ unsigned long long ffma2(
    unsigned long long a, unsigned long long b, unsigned long long c) {
    unsigned long long d;
    asm("fma.rn.f32x2 %0, %1, %2, %3;" : "=l"(d) : "l"(a), "l"(b), "l"(c));
    return d;
}
__device__ __forceinline__ unsigned long long addf2(
    unsigned long long a, unsigned long long b) {
    unsigned long long d;
    asm("add.rn.f32x2 %0, %1, %2;" : "=l"(d) : "l"(a), "l"(b));
    return d;
}
__device__ __forceinline__ unsigned long long packf2(float x, float y) {
    unsigned long long p;
    asm("mov.b64 %0, {%1, %2};" : "=l"(p) : "f"(x), "f"(y));
    return p;
}
__device__ __forceinline__ void unpackf2(unsigned long long p, float& x, float& y) {
    asm("mov.b64 {%0, %1}, %2;" : "=f"(x), "=f"(y) : "l"(p));
}
__device__ __forceinline__ float pair_sum(unsigned long long p) {
    float lo, hi;
    asm("mov.b64 {%0, %1}, %2;" : "=f"(lo), "=f"(hi) : "l"(p));
    return lo + hi;
}

// ---------------------------------------------------------------------------
// Phase 1: xin[t][u] = sum_d x[t][d] * wax[u][d] + ba[u]
// block (0,0) also resets the scan barrier counters (every replay).
// ---------------------------------------------------------------------------
__global__ __launch_bounds__(256) void xin_gemm_kernel(
    const float* __restrict__ x,     // [8192][512]
    const float* __restrict__ wax,   // [2048][512]
    const float* __restrict__ ba)    // [2048]
{
    if (blockIdx.x == 0 && blockIdx.y == 0) {
        for (int i = threadIdx.x; i < NCTR * CTR_STRIDE; i += 256)
            g_ctrs[i] = 0u;
    }

    __shared__ float As[16][128 + 4];
    __shared__ float Bs[16][64 + 4];

    const int tid = threadIdx.x;
    const int bm = blockIdx.y * 128;
    const int bn = blockIdx.x * 64;
    const int tx = tid & 15;
    const int ty = tid >> 4;

    float acc[8][4];
#pragma unroll
    for (int i = 0; i < 8; i++)
#pragma unroll
        for (int j = 0; j < 4; j++) acc[i][j] = 0.f;

    const int lr = tid >> 2;
    const int lc = (tid & 3) * 4;

    for (int k0 = 0; k0 < IN_DIM; k0 += 16) {
        float4 a0 = *(const float4*)&x[(size_t)(bm + lr) * IN_DIM + k0 + lc];
        float4 a1 = *(const float4*)&x[(size_t)(bm + lr + 64) * IN_DIM + k0 + lc];
        float4 b0 = *(const float4*)&wax[(size_t)(bn + lr) * IN_DIM + k0 + lc];

        As[lc + 0][lr] = a0.x; As[lc + 1][lr] = a0.y;
        As[lc + 2][lr] = a0.z; As[lc + 3][lr] = a0.w;
        As[lc + 0][lr + 64] = a1.x; As[lc + 1][lr + 64] = a1.y;
        As[lc + 2][lr + 64] = a1.z; As[lc + 3][lr + 64] = a1.w;
        Bs[lc + 0][lr] = b0.x; Bs[lc + 1][lr] = b0.y;
        Bs[lc + 2][lr] = b0.z; Bs[lc + 3][lr] = b0.w;
        __syncthreads();

#pragma unroll
        for (int kk = 0; kk < 16; kk++) {
            float4 av0 = *(const float4*)&As[kk][ty * 8];
            float4 av1 = *(const float4*)&As[kk][ty * 8 + 4];
            float4 bv  = *(const float4*)&Bs[kk][tx * 4];
            float a[8] = {av0.x, av0.y, av0.z, av0.w, av1.x, av1.y, av1.z, av1.w};
            float b[4] = {bv.x, bv.y, bv.z, bv.w};
#pragma unroll
            for (int i = 0; i < 8; i++)
#pragma unroll
                for (int j = 0; j < 4; j++)
                    acc[i][j] = fmaf(a[i], b[j], acc[i][j]);
        }
        __syncthreads();
    }

    float4 bav = *(const float4*)&ba[bn + tx * 4];
#pragma unroll
    for (int i = 0; i < 8; i++) {
        float4 c;
        c.x = acc[i][0] + bav.x;
        c.y = acc[i][1] + bav.y;
        c.z = acc[i][2] + bav.z;
        c.w = acc[i][3] + bav.w;
        *(float4*)&g_xin[(size_t)(bm + ty * 8 + i) * UNITS + bn + tx * 4] = c;
    }
}

// ---------------------------------------------------------------------------
// Phase 2: persistent scan — 16-way split barrier + SMEM staging.
// 128 CTAs x 256 threads; CTA owns 16 rows, warp w owns rows {16c+2w, +1};
// lane holds cols {128k+4l..+3} for both rows (f32x2 packed, 128 regs).
// Per step t>0:
//   ALL warps poll: lane l reads g_ctrs[(l&15)*32] (one load instr, 16
//   lines) until __all_sync(v >= 8t). No fence (R11-validated).
//   -> each thread stages its 2 float4 of out[t-1] into SMEM (state read
//   ONCE per CTA: 1MB/step from L2 instead of 8MB — kills the 97.5% L2/HBM
//   read pressure seen in R13's profile) -> __syncthreads
//   -> 64 FFMA2/lane from SMEM (crossbar overlapped with FMA issue)
//   -> packed f32x2 butterfly -> lane0: +xin, tanh x2, 8B store
//   -> __syncthreads -> tid0: red.release.add on counter (cta&15)
//   (8 REDs/line drained in parallel across 16 LTS slices).
// ---------------------------------------------------------------------------
__global__ __launch_bounds__(SCAN_THREADS, 1) void scan_kernel(
    const float* __restrict__ waa,   // [2048][2048]
    float* __restrict__ out)         // [8192][2048]
{
    __shared__ float a_sm[UNITS];    // 8 KB state
    float4* a_sm4 = (float4*)a_sm;

    const int tid  = threadIdx.x;
    const int lane = tid & 31;
    const int warp = tid >> 5;               // 0..7
    const int cta  = blockIdx.x;             // 0..127
    const int row0 = cta * 16 + warp * 2;

    // Preload weights packed as f32x2
    unsigned long long w0[16][2], w1[16][2];
#pragma unroll
    for (int k = 0; k < 16; k++) {
        float4 f0 = *(const float4*)&waa[(size_t)row0 * UNITS + k * 128 + lane * 4];
        float4 f1 = *(const float4*)&waa[(size_t)(row0 + 1) * UNITS + k * 128 + lane * 4];
        w0[k][0] = packf2(f0.x, f0.y); w0[k][1] = packf2(f0.z, f0.w);
        w1[k][0] = packf2(f1.x, f1.y); w1[k][1] = packf2(f1.z, f1.w);
    }

    const unsigned* poll_addr = &g_ctrs[(lane & 15) * CTR_STRIDE];
    unsigned* my_ctr = &g_ctrs[(cta & 15) * CTR_STRIDE];

    for (int t = 0; t < TSTEPS; t++) {
        // lane0 prefetches this warp's xin pair (independent of the wait)
        float2 xv;
        if (lane == 0)
            xv = *(const float2*)&g_xin[(size_t)t * UNITS + row0];

        if (t > 0) {
            // every warp polls (one broadcast load instr over 16 lines)
            const unsigned target = (unsigned)t * 8u;   // 8 CTAs per counter
            for (;;) {
                unsigned v = ld_relaxed_gpu(poll_addr);
                if (__all_sync(0xffffffffu, v >= target)) break;
            }
            // stage state ONCE per CTA (coalesced, distinct per thread)
            const float4* aprev = (const float4*)(out + (size_t)(t - 1) * UNITS);
            a_sm4[tid]       = aprev[tid];
            a_sm4[tid + 256] = aprev[tid + 256];
        } else {
            a_sm4[tid]       = make_float4(0.f, 0.f, 0.f, 0.f);
            a_sm4[tid + 256] = make_float4(0.f, 0.f, 0.f, 0.f);
        }
        __syncthreads();   // state staged

        // 2 rows x 2048 cols: 64 FFMA2 per lane, 4 independent chains
        unsigned long long acc0a = 0ull, acc0b = 0ull;
        unsigned long long acc1a = 0ull, acc1b = 0ull;
#pragma unroll
        for (int k = 0; k < 16; k++) {
            float4 av = a_sm4[k * 32 + lane];
            unsigned long long pa = packf2(av.x, av.y);
            unsigned long long pb = packf2(av.z, av.w);
            acc0a = ffma2(w0[k][0], pa, acc0a);
            acc0b = ffma2(w0[k][1], pb, acc0b);
            acc1a = ffma2(w1[k][0], pa, acc1a);
            acc1b = ffma2(w1[k][1], pb, acc1b);
        }
        unsigned long long accA = addf2(acc0a, acc0b);  // (s0lo, s0hi)
        unsigned long long accB = addf2(acc1a, acc1b);  // (s1lo, s1hi)
        unsigned long long s01 = packf2(pair_sum(accA), pair_sum(accB));

        // packed butterfly: 5 stages, 64-bit shfl + f32x2 add
#pragma unroll
        for (int off = 16; off; off >>= 1)
            s01 = addf2(s01, __shfl_xor_sync(0xffffffffu, s01, off));

        if (lane == 0) {
            unsigned long long xp = packf2(xv.x, xv.y);
            unsigned long long r  = addf2(s01, xp);
            float r0, r1;
            unpackf2(r, r0, r1);
            float2 h;
            h.x = tanhf(r0);
            h.y = tanhf(r1);
            *(float2*)&out[(size_t)t * UNITS + row0] = h;
        }

        __syncthreads();   // all 16 outputs stored before the release
        if (tid == 0)
            red_release_add(my_ctr, 1u);
    }
}

// ---------------------------------------------------------------------------
extern "C" void kernel_launch(void* const* d_in, const int* in_sizes, int n_in,
                              void* d_out, int out_size) {
    const float* x   = (const float*)d_in[0];   // (1, 8192, 512)
    const float* waa = (const float*)d_in[1];   // (2048, 2048)
    const float* wax = (const float*)d_in[2];   // (2048, 512)
    const float* ba  = (const float*)d_in[3];   // (2048, 1)
    float* out = (float*)d_out;                 // (1, 8192, 2048)

    dim3 grid(UNITS / 64, TSTEPS / 128);        // (32, 64)
    xin_gemm_kernel<<<grid, 256>>>(x, wax, ba); // also resets g_ctrs

    scan_kernel<<<NCTA, SCAN_THREADS>>>(waa, out);
}

// round 16
// speedup vs baseline: 2.0329x; 2.0329x over previous
#include <cuda_runtime.h>
#include <cstdint>

#define UNITS   2048
#define IN_DIM  512
#define TSTEPS  8192
#define NCTA    128
#define SCAN_THREADS 256
#define NCTR    16          // counters, one 128B line each
#define CTR_STRIDE 32       // 32 uints = 128B

// 64 MB staging buffer for xin = x @ wax^T + ba
__device__ float g_xin[(size_t)TSTEPS * UNITS];
// 16 counting barriers on distinct L2 lines: CTA i bumps counter i&15.
// Step t complete <=> every counter >= 8*t.
__device__ unsigned g_ctrs[NCTR * CTR_STRIDE];

__device__ __forceinline__ unsigned ld_relaxed_gpu(const unsigned* p) {
    unsigned v;
    asm volatile("ld.relaxed.gpu.u32 %0, [%1];" : "=r"(v) : "l"(p) : "memory");
    return v;
}
__device__ __forceinline__ void red_release_add(unsigned* p, unsigned v) {
    asm volatile("red.release.gpu.global.add.u32 [%0], %1;"
                 :: "l"(p), "r"(v) : "memory");
}
__device__ __forceinline__ unsigned long long ffma2(
    unsigned long long a, unsigned long long b, unsigned long long c) {
    unsigned long long d;
    asm("fma.rn.f32x2 %0, %1, %2, %3;" : "=l"(d) : "l"(a), "l"(b), "l"(c));
    return d;
}
__device__ __forceinline__ unsigned long long packf2(float x, float y) {
    unsigned long long p;
    asm("mov.b64 %0, {%1, %2};" : "=l"(p) : "f"(x), "f"(y));
    return p;
}
__device__ __forceinline__ float pair_sum(unsigned long long p) {
    float lo, hi;
    asm("mov.b64 {%0, %1}, %2;" : "=f"(lo), "=f"(hi) : "l"(p));
    return lo + hi;
}

// ---------------------------------------------------------------------------
// Phase 1: xin[t][u] = sum_d x[t][d] * wax[u][d] + ba[u]
// block (0,0) also resets the scan barrier counters (every replay).
// ---------------------------------------------------------------------------
__global__ __launch_bounds__(256) void xin_gemm_kernel(
    const float* __restrict__ x,     // [8192][512]
    const float* __restrict__ wax,   // [2048][512]
    const float* __restrict__ ba)    // [2048]
{
    if (blockIdx.x == 0 && blockIdx.y == 0) {
        for (int i = threadIdx.x; i < NCTR * CTR_STRIDE; i += 256)
            g_ctrs[i] = 0u;
    }

    __shared__ float As[16][128 + 4];
    __shared__ float Bs[16][64 + 4];

    const int tid = threadIdx.x;
    const int bm = blockIdx.y * 128;
    const int bn = blockIdx.x * 64;
    const int tx = tid & 15;
    const int ty = tid >> 4;

    float acc[8][4];
#pragma unroll
    for (int i = 0; i < 8; i++)
#pragma unroll
        for (int j = 0; j < 4; j++) acc[i][j] = 0.f;

    const int lr = tid >> 2;
    const int lc = (tid & 3) * 4;

    for (int k0 = 0; k0 < IN_DIM; k0 += 16) {
        float4 a0 = *(const float4*)&x[(size_t)(bm + lr) * IN_DIM + k0 + lc];
        float4 a1 = *(const float4*)&x[(size_t)(bm + lr + 64) * IN_DIM + k0 + lc];
        float4 b0 = *(const float4*)&wax[(size_t)(bn + lr) * IN_DIM + k0 + lc];

        As[lc + 0][lr] = a0.x; As[lc + 1][lr] = a0.y;
        As[lc + 2][lr] = a0.z; As[lc + 3][lr] = a0.w;
        As[lc + 0][lr + 64] = a1.x; As[lc + 1][lr + 64] = a1.y;
        As[lc + 2][lr + 64] = a1.z; As[lc + 3][lr + 64] = a1.w;
        Bs[lc + 0][lr] = b0.x; Bs[lc + 1][lr] = b0.y;
        Bs[lc + 2][lr] = b0.z; Bs[lc + 3][lr] = b0.w;
        __syncthreads();

#pragma unroll
        for (int kk = 0; kk < 16; kk++) {
            float4 av0 = *(const float4*)&As[kk][ty * 8];
            float4 av1 = *(const float4*)&As[kk][ty * 8 + 4];
            float4 bv  = *(const float4*)&Bs[kk][tx * 4];
            float a[8] = {av0.x, av0.y, av0.z, av0.w, av1.x, av1.y, av1.z, av1.w};
            float b[4] = {bv.x, bv.y, bv.z, bv.w};
#pragma unroll
            for (int i = 0; i < 8; i++)
#pragma unroll
                for (int j = 0; j < 4; j++)
                    acc[i][j] = fmaf(a[i], b[j], acc[i][j]);
        }
        __syncthreads();
    }

    float4 bav = *(const float4*)&ba[bn + tx * 4];
#pragma unroll
    for (int i = 0; i < 8; i++) {
        float4 c;
        c.x = acc[i][0] + bav.x;
        c.y = acc[i][1] + bav.y;
        c.z = acc[i][2] + bav.z;
        c.w = acc[i][3] + bav.w;
        *(float4*)&g_xin[(size_t)(bm + ty * 8 + i) * UNITS + bn + tx * 4] = c;
    }
}

// ---------------------------------------------------------------------------
// Phase 2: persistent scan — COLUMN-SPLIT matvec, split-counter barrier.
// 128 CTAs x 256 threads; CTA owns 16 output rows urow0=16*cta..+15.
// Warp w owns columns [w*256,(w+1)*256); lane owns 8 cols (col0=w*256+l*8)
// for ALL 16 rows: 64 f32x2 weight pairs in regs. The state is read ONCE
// per CTA (8KB total, 1MB/step chip-wide vs R13's 8MB — the 97.5% L2
// bandwidth saturation in R13's profile).
// Per step t>0:
//   warp0 polls g_ctrs[(lane&15)*32] (one 16-line load instr — the only
//   poll shape that doesn't poison L1tex) until __all_sync(v>=8t); no
//   fence (R11-validated) -> __syncthreads ->
//   each lane: 2 LDG.128 of its 8 state values -> 16 rows x 4 FFMA2 ->
//   16 pair_sums -> value-halving fold (31 shfl, SELECTS USE CONSTANT
//   INDICES ONLY -> SEL not LDL, no spills) -> even lanes write
//   red_sm[warp][row] -> __syncthreads -> warp0 lanes 0-15: sum 8
//   partials + xin, tanh, 64B coalesced store of out[t] ->
//   __syncthreads -> tid0: red.release.add counter (cta&15).
// ---------------------------------------------------------------------------
__global__ __launch_bounds__(SCAN_THREADS, 1) void scan_kernel(
    const float* __restrict__ waa,   // [2048][2048]
    float* __restrict__ out)         // [8192][2048]
{
    __shared__ float red_sm[8][16];

    const int tid  = threadIdx.x;
    const int lane = tid & 31;
    const int warp = tid >> 5;               // 0..7
    const int cta  = blockIdx.x;             // 0..127
    const int urow0 = cta * 16;
    const int col0  = warp * 256 + lane * 8; // this lane's 8 columns

    // Preload weights: wp[r][p] = waa[urow0+r][col0+2p .. +2p+1] packed
    unsigned long long wp[16][4];
#pragma unroll
    for (int r = 0; r < 16; r++) {
        const float* wr = &waa[(size_t)(urow0 + r) * UNITS + col0];
        float4 fa = *(const float4*)(wr);
        float4 fb = *(const float4*)(wr + 4);
        wp[r][0] = packf2(fa.x, fa.y);
        wp[r][1] = packf2(fa.z, fa.w);
        wp[r][2] = packf2(fb.x, fb.y);
        wp[r][3] = packf2(fb.z, fb.w);
    }

    // this lane's output row after the fold (bit pattern of the selects)
    const int myrow = ((lane & 16) ? 8 : 0) | ((lane & 8) ? 4 : 0) |
                      ((lane & 4) ? 2 : 0) | ((lane & 2) ? 1 : 0);

    const unsigned* poll_addr = &g_ctrs[(lane & 15) * CTR_STRIDE];
    unsigned* my_ctr = &g_ctrs[(cta & 15) * CTR_STRIDE];

    for (int t = 0; t < TSTEPS; t++) {
        // warp0 prefetches xin for the final reduce (independent of wait)
        float xv = 0.f;
        if (warp == 0 && lane < 16)
            xv = __ldg(&g_xin[(size_t)t * UNITS + urow0 + lane]);

        if (t > 0) {
            if (warp == 0) {
                const unsigned target = (unsigned)t * 8u;  // 8 CTAs per counter
                for (;;) {
                    unsigned v = ld_relaxed_gpu(poll_addr);
                    if (__all_sync(0xffffffffu, v >= target)) break;
                }
            }
            __syncthreads();   // gate all warps on the fresh state

            // lane's 8 state values: 2 x LDG.128 (state read ONCE per CTA)
            const float* ab = out + (size_t)(t - 1) * UNITS + col0;
            float4 av0 = *(const float4*)(ab);
            float4 av1 = *(const float4*)(ab + 4);
            unsigned long long pa0 = packf2(av0.x, av0.y);
            unsigned long long pa1 = packf2(av0.z, av0.w);
            unsigned long long pa2 = packf2(av1.x, av1.y);
            unsigned long long pa3 = packf2(av1.z, av1.w);

            // 16 rows x 4 chained FFMA2 (rows independent -> ILP=16)
            float v[16];
#pragma unroll
            for (int r = 0; r < 16; r++) {
                unsigned long long s = ffma2(wp[r][0], pa0, 0ull);
                s = ffma2(wp[r][1], pa1, s);
                s = ffma2(wp[r][2], pa2, s);
                s = ffma2(wp[r][3], pa3, s);
                v[r] = pair_sum(s);
            }

            // value-halving fold; all selects use CONSTANT indices (SEL)
#pragma unroll
            for (int i = 0; i < 16; i++)
                v[i] += __shfl_xor_sync(0xffffffffu, v[i], 16);
            float u8[8];
#pragma unroll
            for (int i = 0; i < 8; i++)
                u8[i] = (lane & 16) ? v[i + 8] : v[i];
#pragma unroll
            for (int i = 0; i < 8; i++)
                u8[i] += __shfl_xor_sync(0xffffffffu, u8[i], 8);
            float u4[4];
#pragma unroll
            for (int i = 0; i < 4; i++)
                u4[i] = (lane & 8) ? u8[i + 4] : u8[i];
#pragma unroll
            for (int i = 0; i < 4; i++)
                u4[i] += __shfl_xor_sync(0xffffffffu, u4[i], 4);
            float u2[2];
            u2[0] = (lane & 4) ? u4[2] : u4[0];
            u2[1] = (lane & 4) ? u4[3] : u4[1];
            u2[0] += __shfl_xor_sync(0xffffffffu, u2[0], 2);
            u2[1] += __shfl_xor_sync(0xffffffffu, u2[1], 2);
            float y = (lane & 2) ? u2[1] : u2[0];
            y += __shfl_xor_sync(0xffffffffu, y, 1);

            if (!(lane & 1)) red_sm[warp][myrow] = y;
        } else {
            if (!(lane & 1)) red_sm[warp][myrow] = 0.f;
        }
        __syncthreads();   // red_sm ready

        if (warp == 0 && lane < 16) {
            float s = xv;
#pragma unroll
            for (int w = 0; w < 8; w++) s += red_sm[w][lane];
            out[(size_t)t * UNITS + urow0 + lane] = tanhf(s);
        }

        __syncthreads();   // outputs stored before release; red_sm reusable
        if (tid == 0)
            red_release_add(my_ctr, 1u);
    }
}

// ---------------------------------------------------------------------------
extern "C" void kernel_launch(void* const* d_in, const int* in_sizes, int n_in,
                              void* d_out, int out_size) {
    const float* x   = (const float*)d_in[0];   // (1, 8192, 512)
    const float* waa = (const float*)d_in[1];   // (2048, 2048)
    const float* wax = (const float*)d_in[2];   // (2048, 512)
    const float* ba  = (const float*)d_in[3];   // (2048, 1)
    float* out = (float*)d_out;                 // (1, 8192, 2048)

    dim3 grid(UNITS / 64, TSTEPS / 128);        // (32, 64)
    xin_gemm_kernel<<<grid, 256>>>(x, wax, ba); // also resets g_ctrs

    scan_kernel<<<NCTA, SCAN_THREADS>>>(waa, out);
}